// round 1
// baseline (speedup 1.0000x reference)
#include <cuda_runtime.h>
#include <math.h>

#define BB 4
#define CH 128
#define HW 4096
#define LPOS (BB*HW)     // 16384 positions total
#define DINP 644
#define DI 256
#define NH 4
#define HD 64
#define DS 64
#define CC 384

// ---------------- scratch (device globals; no allocation allowed) ----------
__device__ float g_normed[(size_t)LPOS*CH];          // 8.4 MB
__device__ float g_zx[(size_t)LPOS*DINP];            // 42 MB
__device__ float g_xbc[(size_t)LPOS*CC];             // 25 MB
__device__ float g_dt[(size_t)LPOS*NH];
__device__ float g_yp[(size_t)LPOS*NH*256];          // 67 MB: 4 partials per (p,t)
__device__ float g_gate[(size_t)LPOS*DI];            // 16.8 MB
__device__ float g_res[(size_t)LPOS*CH];             // 8.4 MB
__device__ float g_ff1[(size_t)LPOS*CH];             // 8.4 MB

// ---------------- 1. LayerNorm over channels (transposed gather) ----------
__global__ void ln_kernel(const float* __restrict__ noisy,
                          const float* __restrict__ gamma,
                          const float* __restrict__ beta) {
    int warp = threadIdx.x >> 5, lane = threadIdx.x & 31;
    int pos = blockIdx.x * 8 + warp;            // 0..16383
    int b = pos >> 12, sp = pos & 4095;
    const float* src = noisy + (size_t)b*CH*HW + sp;
    float v[4]; float s = 0.f, s2 = 0.f;
#pragma unroll
    for (int i = 0; i < 4; i++) {
        int c = lane + 32*i;
        v[i] = src[(size_t)c*HW];
        s += v[i]; s2 += v[i]*v[i];
    }
#pragma unroll
    for (int o = 16; o > 0; o >>= 1) {
        s  += __shfl_xor_sync(0xffffffffu, s,  o);
        s2 += __shfl_xor_sync(0xffffffffu, s2, o);
    }
    float mean = s * (1.f/128.f);
    float var  = s2 * (1.f/128.f) - mean*mean;
    float inv  = rsqrtf(var + 1e-5f);
#pragma unroll
    for (int i = 0; i < 4; i++) {
        int c = lane + 32*i;
        g_normed[(size_t)pos*CH + c] = (v[i]-mean)*inv*gamma[c] + beta[c];
    }
}

// ---------------- 2. in_proj GEMM: (16384x128) @ (644x128)^T -> g_zx ------
__global__ void gemm_inproj(const float* __restrict__ W) {
    __shared__ float As[16][64];
    __shared__ float Ws[16][68];
    int bm = blockIdx.y * 64, bn = blockIdx.x * 64;
    int tx = threadIdx.x & 15, ty = threadIdx.x >> 4;
    float acc[4][4] = {};
    for (int k0 = 0; k0 < CH; k0 += 16) {
#pragma unroll
        for (int i = 0; i < 4; i++) {
            int t = threadIdx.x + i*256; int m = t >> 4, kk = t & 15;
            As[kk][m] = g_normed[(size_t)(bm+m)*CH + k0 + kk];
        }
#pragma unroll
        for (int i = 0; i < 4; i++) {
            int t = threadIdx.x + i*256; int n = t >> 4, kk = t & 15;
            Ws[kk][n] = (bn+n < DINP) ? W[(size_t)(bn+n)*CH + k0 + kk] : 0.f;
        }
        __syncthreads();
#pragma unroll
        for (int kk = 0; kk < 16; kk++) {
            float a[4], wv[4];
#pragma unroll
            for (int i = 0; i < 4; i++) { a[i] = As[kk][ty*4+i]; wv[i] = Ws[kk][tx*4+i]; }
#pragma unroll
            for (int i = 0; i < 4; i++)
#pragma unroll
                for (int j = 0; j < 4; j++) acc[i][j] += a[i]*wv[j];
        }
        __syncthreads();
    }
#pragma unroll
    for (int i = 0; i < 4; i++)
#pragma unroll
        for (int j = 0; j < 4; j++) {
            int n = bn + tx*4 + j;
            if (n < DINP) g_zx[(size_t)(bm + ty*4 + i)*DINP + n] = acc[i][j];
        }
}

// ---------------- 3. causal depthwise conv1d (k=5) + bias + SiLU ----------
__global__ void conv1d_kernel(const float* __restrict__ cw, const float* __restrict__ cb) {
    __shared__ float s[68][128];
    int b = blockIdx.z, ct = blockIdx.y * 128, p0 = blockIdx.x * 64;
    const float* zxb = g_zx + (size_t)b*HW*DINP;
    for (int idx = threadIdx.x; idx < 68*128; idx += 256) {
        int r = idx >> 7, c = idx & 127;
        int pos = p0 - 4 + r;
        s[r][c] = (pos >= 0) ? zxb[(size_t)pos*DINP + DI + ct + c] : 0.f;
    }
    __syncthreads();
    for (int idx = threadIdx.x; idx < 64*128; idx += 256) {
        int r = idx >> 7, c = idx & 127;
        int ch = ct + c;
        float acc = cb[ch];
#pragma unroll
        for (int k = 0; k < 5; k++) acc += s[r+k][c] * cw[ch*5 + k];
        float o = acc / (1.f + expf(-acc));
        g_xbc[((size_t)b*HW + p0 + r)*CC + ch] = o;
    }
}

// ---------------- 3b. dt = softplus(raw + bias) ---------------------------
__global__ void dt_kernel(const float* __restrict__ dtb) {
    int idx = blockIdx.x*256 + threadIdx.x;
    if (idx >= LPOS*NH) return;
    int h = idx & 3;
    float v = g_zx[(size_t)(idx >> 2)*DINP + 640 + h] + dtb[h];
    g_dt[idx] = (v > 20.f) ? v : log1pf(expf(v));
}

// ---------------- 4. selective scan -----------------------------------
// 128 blocks x 32 threads. block = (b, h, p-group of 8). lane = (p_local, n-quarter).
// Each lane owns 16 n-states in registers; writes a PARTIAL y per step (no shfl);
// gate kernel sums the 4 partials. Depth-2 register prefetch of B/C/x/dt.
struct Pf { float bb[16], cc[16], x, dt; };

__device__ __forceinline__ void pf_load(Pf& P, const float* row, int n0, int hp,
                                        const float* dtp) {
#pragma unroll
    for (int i = 0; i < 4; i++) {
        *(float4*)&P.bb[4*i] = *(const float4*)(row + DI + n0 + 4*i);
        *(float4*)&P.cc[4*i] = *(const float4*)(row + DI + DS + n0 + 4*i);
    }
    P.x = row[hp];
    P.dt = *dtp;
}

__global__ void __launch_bounds__(32) scan_kernel(const float* __restrict__ Alog) {
    int bid = blockIdx.x;
    int b = bid >> 5, h = (bid >> 3) & 3, pg = bid & 7;
    int lane = threadIdx.x;
    int pl = lane >> 2, ln = lane & 3;
    int p = pg*8 + pl, n0 = ln*16;
    int hp = h*HD + p;
    const float* base = g_xbc + (size_t)b*HW*CC;
    const float* dtp  = g_dt  + (size_t)b*HW*NH + h;
    float* out = g_yp + (size_t)b*HW*NH*256 + h*256 + pg*32 + lane;
    float Ah = -expf(Alog[h]);
    float st[16];
#pragma unroll
    for (int i = 0; i < 16; i++) st[i] = 0.f;

    Pf A, Bq;
    pf_load(A, base, n0, hp, dtp);
    for (int t = 0; t < HW; t += 2) {
        pf_load(Bq, base + (size_t)(t+1)*CC, n0, hp, dtp + (size_t)(t+1)*NH);
        {
            float dA = expf(A.dt * Ah), coef = A.dt * A.x;
            float a0 = 0.f, a1 = 0.f;
#pragma unroll
            for (int i = 0; i < 16; i++) {
                st[i] = st[i]*dA + coef*A.bb[i];
                if (i < 8) a0 += st[i]*A.cc[i]; else a1 += st[i]*A.cc[i];
            }
            out[(size_t)t*(NH*256)] = a0 + a1;
        }
        if (t + 2 < HW) pf_load(A, base + (size_t)(t+2)*CC, n0, hp, dtp + (size_t)(t+2)*NH);
        {
            float dA = expf(Bq.dt * Ah), coef = Bq.dt * Bq.x;
            float a0 = 0.f, a1 = 0.f;
#pragma unroll
            for (int i = 0; i < 16; i++) {
                st[i] = st[i]*dA + coef*Bq.bb[i];
                if (i < 8) a0 += st[i]*Bq.cc[i]; else a1 += st[i]*Bq.cc[i];
            }
            out[(size_t)(t+1)*(NH*256)] = a0 + a1;
        }
    }
}

// ---------------- 5. sum partials + D-skip + gate(silu(z)) + RMSNorm ------
__global__ void gate_kernel(const float* __restrict__ Dsk, const float* __restrict__ rmsw) {
    int warp = threadIdx.x >> 5, lane = threadIdx.x & 31;
    int pos = blockIdx.x * 8 + warp;
    const float* zrow  = g_zx  + (size_t)pos*DINP;
    const float* xrow  = g_xbc + (size_t)pos*CC;
    const float* yprow = g_yp  + (size_t)pos*NH*256;
    float gv[8]; float ss = 0.f;
#pragma unroll
    for (int i = 0; i < 8; i++) {
        int c = lane + 32*i; int h = c >> 6;
        float4 pp = *(const float4*)(yprow + h*256 + (c & 63)*4);
        float y = pp.x + pp.y + pp.z + pp.w + Dsk[h]*xrow[c];
        float z = zrow[c];
        float g = y * (z / (1.f + expf(-z)));
        gv[i] = g; ss += g*g;
    }
#pragma unroll
    for (int o = 16; o > 0; o >>= 1) ss += __shfl_xor_sync(0xffffffffu, ss, o);
    float sc = rsqrtf(ss*(1.f/256.f) + 1e-5f);
#pragma unroll
    for (int i = 0; i < 8; i++) {
        int c = lane + 32*i;
        g_gate[(size_t)pos*DI + c] = gv[i]*sc*rmsw[c];
    }
}

// ---------------- 6. out_proj GEMM + residual + transpose to (b,c,h,w) ----
__global__ void gemm_out(const float* __restrict__ W, const float* __restrict__ noisy) {
    __shared__ float As[16][64];
    __shared__ float Ws[16][68];
    __shared__ float sOut[64][65];
    int bm = blockIdx.y * 64, bn = blockIdx.x * 64;
    int tx = threadIdx.x & 15, ty = threadIdx.x >> 4;
    float acc[4][4] = {};
    for (int k0 = 0; k0 < DI; k0 += 16) {
#pragma unroll
        for (int i = 0; i < 4; i++) {
            int t = threadIdx.x + i*256; int m = t >> 4, kk = t & 15;
            As[kk][m] = g_gate[(size_t)(bm+m)*DI + k0 + kk];
        }
#pragma unroll
        for (int i = 0; i < 4; i++) {
            int t = threadIdx.x + i*256; int n = t >> 4, kk = t & 15;
            Ws[kk][n] = W[(size_t)(bn+n)*DI + k0 + kk];
        }
        __syncthreads();
#pragma unroll
        for (int kk = 0; kk < 16; kk++) {
            float a[4], wv[4];
#pragma unroll
            for (int i = 0; i < 4; i++) { a[i] = As[kk][ty*4+i]; wv[i] = Ws[kk][tx*4+i]; }
#pragma unroll
            for (int i = 0; i < 4; i++)
#pragma unroll
                for (int j = 0; j < 4; j++) acc[i][j] += a[i]*wv[j];
        }
        __syncthreads();
    }
#pragma unroll
    for (int i = 0; i < 4; i++)
#pragma unroll
        for (int j = 0; j < 4; j++) sOut[tx*4+j][ty*4+i] = acc[i][j];
    __syncthreads();
    for (int r = 0; r < 16; r++) {
        int nl = r*4 + (threadIdx.x >> 6), ml = threadIdx.x & 63;
        int pos = bm + ml, c = bn + nl;
        int b = pos >> 12, sp = pos & 4095;
        size_t o = ((size_t)(b*CH + c))*HW + sp;
        g_res[o] = noisy[o] + sOut[nl][ml];
    }
}

// ---------------- 7/8. 3x3 conv (reflect pad) + ReLU [+ residual to out] ---
__global__ void conv3_kernel(const float* __restrict__ in, const float* __restrict__ w,
                             const float* __restrict__ bias, float* __restrict__ out,
                             const float* __restrict__ resid) {
    __shared__ float sIn[16][18][34];
    __shared__ float sW[8][16][9];
    int b = blockIdx.z, co0 = blockIdx.y * 8;
    int bx = blockIdx.x & 1, by = blockIdx.x >> 1;
    int x0 = bx*32, y0 = by*16;
    int x = threadIdx.x & 31, ty = threadIdx.x >> 5;
    float acc[2][8];
#pragma unroll
    for (int px = 0; px < 2; px++)
#pragma unroll
        for (int co = 0; co < 8; co++) acc[px][co] = bias[co0+co];

    for (int ci0 = 0; ci0 < CH; ci0 += 16) {
        for (int idx = threadIdx.x; idx < 16*18*34; idx += 256) {
            int ci = idx / 612; int rem = idx - ci*612;
            int yy = rem / 34;  int xx = rem - yy*34;
            int iy = y0 + yy - 1; iy = iy < 0 ? -iy : (iy >= 64 ? 126 - iy : iy);
            int ix = x0 + xx - 1; ix = ix < 0 ? -ix : (ix >= 64 ? 126 - ix : ix);
            sIn[ci][yy][xx] = in[(((size_t)b*CH + ci0 + ci)*64 + iy)*64 + ix];
        }
        for (int idx = threadIdx.x; idx < 8*16*9; idx += 256) {
            int co = idx / 144; int rem = idx - co*144;
            int ci = rem / 9;   int k = rem - ci*9;
            sW[co][ci][k] = w[((size_t)(co0+co)*CH + ci0 + ci)*9 + k];
        }
        __syncthreads();
#pragma unroll 1
        for (int ci = 0; ci < 16; ci++) {
#pragma unroll
            for (int ky = 0; ky < 3; ky++)
#pragma unroll
                for (int kx = 0; kx < 3; kx++) {
                    float v0 = sIn[ci][ty   + ky][x + kx];
                    float v1 = sIn[ci][ty+8 + ky][x + kx];
#pragma unroll
                    for (int co = 0; co < 8; co++) {
                        float wv = sW[co][ci][ky*3 + kx];
                        acc[0][co] += v0*wv;
                        acc[1][co] += v1*wv;
                    }
                }
        }
        __syncthreads();
    }
#pragma unroll
    for (int px = 0; px < 2; px++)
#pragma unroll
        for (int co = 0; co < 8; co++) {
            float v = fmaxf(acc[px][co], 0.f);
            size_t o = (((size_t)b*CH + co0 + co)*64 + y0 + ty + px*8)*64 + x0 + x;
            out[o] = resid ? resid[o] + v : v;
        }
}

// ---------------- launch ---------------------------------------------------
extern "C" void kernel_launch(void* const* d_in, const int* in_sizes, int n_in,
                              void* d_out, int out_size) {
    const float* noisy = (const float*)d_in[0];
    const float* aux   = (const float*)d_in[1];
    const float* gamma = (const float*)d_in[2];
    const float* beta  = (const float*)d_in[3];
    const float* inw   = (const float*)d_in[4];
    const float* cw    = (const float*)d_in[5];
    const float* cb    = (const float*)d_in[6];
    const float* alog  = (const float*)d_in[7];
    const float* dtb   = (const float*)d_in[8];
    const float* Dsk   = (const float*)d_in[9];
    const float* rmsw  = (const float*)d_in[10];
    const float* outw  = (const float*)d_in[11];
    const float* fw1   = (const float*)d_in[12];
    const float* fb1   = (const float*)d_in[13];
    const float* fw2   = (const float*)d_in[14];
    const float* fb2   = (const float*)d_in[15];
    float* out = (float*)d_out;

    void *p_res, *p_ff1;
    cudaGetSymbolAddress(&p_res, g_res);
    cudaGetSymbolAddress(&p_ff1, g_ff1);

    ln_kernel<<<2048, 256>>>(noisy, gamma, beta);
    gemm_inproj<<<dim3(11, 256), 256>>>(inw);
    conv1d_kernel<<<dim3(64, 3, 4), 256>>>(cw, cb);
    dt_kernel<<<(LPOS*NH + 255)/256, 256>>>(dtb);
    scan_kernel<<<128, 32>>>(alog);
    gate_kernel<<<2048, 256>>>(Dsk, rmsw);
    gemm_out<<<dim3(2, 256), 256>>>(outw, noisy);
    conv3_kernel<<<dim3(8, 16, 4), 256>>>((const float*)p_res, fw1, fb1, (float*)p_ff1, nullptr);
    conv3_kernel<<<dim3(8, 16, 4), 256>>>((const float*)p_ff1, fw2, fb2, out, (const float*)p_res);

    // aux passthrough: second half of output
    if (out_size >= 2*LPOS*CH) {
        cudaMemcpyAsync(out + (size_t)LPOS*CH, aux, (size_t)LPOS*CH*sizeof(float),
                        cudaMemcpyDeviceToDevice, 0);
    }
}

// round 2
// speedup vs baseline: 4.3538x; 4.3538x over previous
#include <cuda_runtime.h>
#include <math.h>

#define BB 4
#define CH 128
#define HW 4096
#define LPOS (BB*HW)     // 16384 positions total
#define DINP 644
#define DI 256
#define NH 4
#define HD 64
#define DS 64
#define CC 384
#define Q 32             // SSD chunk length
#define NCHUNK (HW/Q)    // 128 chunks per (b)

// ---------------- scratch (device globals; no allocation allowed) ----------
__device__ float g_normed[(size_t)LPOS*CH];          // 8.4 MB
__device__ float g_zx[(size_t)LPOS*DINP];            // 42 MB
__device__ float g_xbc[(size_t)LPOS*CC];             // 25 MB
__device__ float g_y[(size_t)LPOS*DI];               // 16.8 MB (scan output)
__device__ float g_U[(size_t)16*NCHUNK*HD*DS];       // 33.5 MB chunk outer sums
__device__ float g_hst[(size_t)16*NCHUNK*HD*DS];     // 33.5 MB chunk start states
__device__ float g_P[(size_t)16*HW];                 // exp(S_t) per (bh,pos)
__device__ float g_D[16*NCHUNK];                     // chunk decay
__device__ float g_gate[(size_t)LPOS*DI];            // 16.8 MB
__device__ float g_res[(size_t)LPOS*CH];             // 8.4 MB
__device__ float g_ff1[(size_t)LPOS*CH];             // 8.4 MB

// ---------------- 1. LayerNorm over channels (transposed gather) ----------
__global__ void ln_kernel(const float* __restrict__ noisy,
                          const float* __restrict__ gamma,
                          const float* __restrict__ beta) {
    int warp = threadIdx.x >> 5, lane = threadIdx.x & 31;
    int pos = blockIdx.x * 8 + warp;            // 0..16383
    int b = pos >> 12, sp = pos & 4095;
    const float* src = noisy + (size_t)b*CH*HW + sp;
    float v[4]; float s = 0.f, s2 = 0.f;
#pragma unroll
    for (int i = 0; i < 4; i++) {
        int c = lane + 32*i;
        v[i] = src[(size_t)c*HW];
        s += v[i]; s2 += v[i]*v[i];
    }
#pragma unroll
    for (int o = 16; o > 0; o >>= 1) {
        s  += __shfl_xor_sync(0xffffffffu, s,  o);
        s2 += __shfl_xor_sync(0xffffffffu, s2, o);
    }
    float mean = s * (1.f/128.f);
    float var  = s2 * (1.f/128.f) - mean*mean;
    float inv  = rsqrtf(var + 1e-5f);
#pragma unroll
    for (int i = 0; i < 4; i++) {
        int c = lane + 32*i;
        g_normed[(size_t)pos*CH + c] = (v[i]-mean)*inv*gamma[c] + beta[c];
    }
}

// ---------------- 2. in_proj GEMM: (16384x128) @ (644x128)^T -> g_zx ------
__global__ void gemm_inproj(const float* __restrict__ W) {
    __shared__ float As[16][64];
    __shared__ float Ws[16][68];
    int bm = blockIdx.y * 64, bn = blockIdx.x * 64;
    int tx = threadIdx.x & 15, ty = threadIdx.x >> 4;
    float acc[4][4] = {};
    for (int k0 = 0; k0 < CH; k0 += 16) {
#pragma unroll
        for (int i = 0; i < 4; i++) {
            int t = threadIdx.x + i*256; int m = t >> 4, kk = t & 15;
            As[kk][m] = g_normed[(size_t)(bm+m)*CH + k0 + kk];
        }
#pragma unroll
        for (int i = 0; i < 4; i++) {
            int t = threadIdx.x + i*256; int n = t >> 4, kk = t & 15;
            Ws[kk][n] = (bn+n < DINP) ? W[(size_t)(bn+n)*CH + k0 + kk] : 0.f;
        }
        __syncthreads();
#pragma unroll
        for (int kk = 0; kk < 16; kk++) {
            float a[4], wv[4];
#pragma unroll
            for (int i = 0; i < 4; i++) { a[i] = As[kk][ty*4+i]; wv[i] = Ws[kk][tx*4+i]; }
#pragma unroll
            for (int i = 0; i < 4; i++)
#pragma unroll
                for (int j = 0; j < 4; j++) acc[i][j] += a[i]*wv[j];
        }
        __syncthreads();
    }
#pragma unroll
    for (int i = 0; i < 4; i++)
#pragma unroll
        for (int j = 0; j < 4; j++) {
            int n = bn + tx*4 + j;
            if (n < DINP) g_zx[(size_t)(bm + ty*4 + i)*DINP + n] = acc[i][j];
        }
}

// ---------------- 3. causal depthwise conv1d (k=5) + bias + SiLU ----------
__global__ void conv1d_kernel(const float* __restrict__ cw, const float* __restrict__ cb) {
    __shared__ float s[68][128];
    int b = blockIdx.z, ct = blockIdx.y * 128, p0 = blockIdx.x * 64;
    const float* zxb = g_zx + (size_t)b*HW*DINP;
    for (int idx = threadIdx.x; idx < 68*128; idx += 256) {
        int r = idx >> 7, c = idx & 127;
        int pos = p0 - 4 + r;
        s[r][c] = (pos >= 0) ? zxb[(size_t)pos*DINP + DI + ct + c] : 0.f;
    }
    __syncthreads();
    for (int idx = threadIdx.x; idx < 64*128; idx += 256) {
        int r = idx >> 7, c = idx & 127;
        int ch = ct + c;
        float acc = cb[ch];
#pragma unroll
        for (int k = 0; k < 5; k++) acc += s[r+k][c] * cw[ch*5 + k];
        float o = acc / (1.f + expf(-acc));
        g_xbc[((size_t)b*HW + p0 + r)*CC + ch] = o;
    }
}

// ---------------- 4a. SSD chunk kernel ------------------------------------
// block = (b, h, c): 2048 blocks x 256 threads.
// Computes (per chunk of Q=32 steps): decay prefix S_t, intra-chunk output
// y_intra (written to g_y), chunk outer-product sum U, exp(S_t), chunk decay D.
__global__ void __launch_bounds__(256) ssd_chunk(const float* __restrict__ Alog,
                                                 const float* __restrict__ dtb) {
    __shared__ float sX[Q*64];        // [s][p]  stride 64
    __shared__ float sB[Q*68];        // [s][n]  stride 68 (later scaled by wU)
    __shared__ float sC[Q*68];        // [s][n]; reused as Ms[s][t] stride 33
    __shared__ float sdt[Q], sS[Q], sWU[Q];

    int bid = blockIdx.x;
    int c  = bid & 127;
    int h  = (bid >> 7) & 3;
    int b  = bid >> 9;
    int bh = b*4 + h;
    int pos0 = b*HW + c*Q;            // global position row base
    int tid = threadIdx.x;
    int tx = tid & 15, ty = tid >> 4;

    // --- load dt, compute log-decay ---
    if (tid < Q) {
        float raw = g_zx[(size_t)(pos0+tid)*DINP + 640 + h] + dtb[h];
        float dt = (raw > 20.f) ? raw : log1pf(expf(raw));
        sdt[tid] = dt;
    }
    // --- load X, B, C tiles ---
    for (int idx = tid; idx < Q*64; idx += 256) {
        int s = idx >> 6, n = idx & 63;
        const float* row = g_xbc + (size_t)(pos0+s)*CC;
        sX[s*64 + n] = row[h*HD + n];
        sB[s*68 + n] = row[DI + n];
        sC[s*68 + n] = row[DI + DS + n];
    }
    __syncthreads();
    // --- prefix sum of log-decay (serial, tiny) ---
    if (tid == 0) {
        float Ah = -expf(Alog[h]);
        float run = 0.f;
#pragma unroll
        for (int s = 0; s < Q; s++) { run += sdt[s]*Ah; sS[s] = run; }
    }
    __syncthreads();
    float Stot = sS[Q-1];
    if (tid < Q) {
        sWU[tid] = expf(Stot - sS[tid]) * sdt[tid];
        g_P[(size_t)bh*HW + c*Q + tid] = expf(sS[tid]);
        if (tid == 0) g_D[bh*NCHUNK + c] = expf(Stot);
    }
    __syncthreads();

    // --- phase M: M[t][s] = sum_n C[t][n]*B[s][n] ---
    float mac[2][2] = {};
#pragma unroll 4
    for (int k0 = 0; k0 < 64; k0 += 4) {
        float4 a0 = *(const float4*)&sC[(ty*2+0)*68 + k0];
        float4 a1 = *(const float4*)&sC[(ty*2+1)*68 + k0];
        float4 b0 = *(const float4*)&sB[(tx*2+0)*68 + k0];
        float4 b1 = *(const float4*)&sB[(tx*2+1)*68 + k0];
        mac[0][0] += a0.x*b0.x + a0.y*b0.y + a0.z*b0.z + a0.w*b0.w;
        mac[0][1] += a0.x*b1.x + a0.y*b1.y + a0.z*b1.z + a0.w*b1.w;
        mac[1][0] += a1.x*b0.x + a1.y*b0.y + a1.z*b0.z + a1.w*b0.w;
        mac[1][1] += a1.x*b1.x + a1.y*b1.y + a1.z*b1.z + a1.w*b1.w;
    }
    __syncthreads();   // everyone done reading sC
    // --- weight M and store into sC space as Ms[s][t], stride 33 ---
    float* sMs = sC;
#pragma unroll
    for (int i = 0; i < 2; i++)
#pragma unroll
        for (int j = 0; j < 2; j++) {
            int t = ty*2+i, s = tx*2+j;
            float wgt = (s <= t) ? expf(sS[t]-sS[s])*sdt[s] : 0.f;
            sMs[s*33 + t] = mac[i][j]*wgt;
        }
    // --- scale B rows by wU for U phase ---
    for (int idx = tid; idx < Q*64; idx += 256) {
        int s = idx >> 6, n = idx & 63;
        sB[s*68 + n] *= sWU[s];
    }
    __syncthreads();

    // --- phase y_intra: y[t][p] = sum_s Ms[s][t]*X[s][p] ---
    {
        float acc[2][4] = {};
#pragma unroll 4
        for (int s = 0; s < Q; s++) {
            float m0 = sMs[s*33 + ty*2+0];
            float m1 = sMs[s*33 + ty*2+1];
            float4 xv = *(const float4*)&sX[s*64 + tx*4];
            acc[0][0] += m0*xv.x; acc[0][1] += m0*xv.y; acc[0][2] += m0*xv.z; acc[0][3] += m0*xv.w;
            acc[1][0] += m1*xv.x; acc[1][1] += m1*xv.y; acc[1][2] += m1*xv.z; acc[1][3] += m1*xv.w;
        }
#pragma unroll
        for (int i = 0; i < 2; i++) {
            int t = ty*2+i;
            float4 o; o.x = acc[i][0]; o.y = acc[i][1]; o.z = acc[i][2]; o.w = acc[i][3];
            *(float4*)&g_y[(size_t)(pos0+t)*DI + h*HD + tx*4] = o;
        }
    }

    // --- phase U: U[p][n] = sum_s X[s][p]*(wU_s*B[s][n]) ---
    {
        float acc[4][4] = {};
#pragma unroll 4
        for (int s = 0; s < Q; s++) {
            float4 av = *(const float4*)&sX[s*64 + ty*4];
            float4 bv = *(const float4*)&sB[s*68 + tx*4];
            float a[4] = {av.x, av.y, av.z, av.w};
            float bb[4] = {bv.x, bv.y, bv.z, bv.w};
#pragma unroll
            for (int i = 0; i < 4; i++)
#pragma unroll
                for (int j = 0; j < 4; j++) acc[i][j] += a[i]*bb[j];
        }
        float* Uo = g_U + ((size_t)bh*NCHUNK + c)*HD*DS;
#pragma unroll
        for (int i = 0; i < 4; i++) {
            int p = ty*4+i;
            float4 o; o.x = acc[i][0]; o.y = acc[i][1]; o.z = acc[i][2]; o.w = acc[i][3];
            *(float4*)&Uo[p*DS + tx*4] = o;
        }
    }
}

// ---------------- 4b. chunk-state recurrence ------------------------------
// h_start(c) then h = D_c*h + U_c.  64 blocks x 1024 threads = 16 bh x 4096 elems.
__global__ void ssd_chain() {
    int e = blockIdx.x*1024 + threadIdx.x;
    int bh = e >> 12, el = e & 4095;
    const float* U = g_U   + (size_t)bh*NCHUNK*4096 + el;
    float*       H = g_hst + (size_t)bh*NCHUNK*4096 + el;
    const float* Dd = g_D + bh*NCHUNK;
    float hval = 0.f;
    float u = U[0], d = Dd[0];
    for (int ci = 0; ci < NCHUNK; ci++) {
        float un = 0.f, dn = 0.f;
        if (ci + 1 < NCHUNK) { un = U[(size_t)(ci+1)*4096]; dn = Dd[ci+1]; }
        H[(size_t)ci*4096] = hval;
        hval = d*hval + u;
        u = un; d = dn;
    }
}

// ---------------- 4c. inter-chunk output: y += exp(S_t) * C_t . h_start ---
__global__ void __launch_bounds__(256) ssd_inter() {
    __shared__ float sH[64*68];      // [p][n] stride 68
    __shared__ float sCw[Q*68];      // [t][n] * exp(S_t)
    __shared__ float sPt[Q];
    int bid = blockIdx.x;
    int c  = bid & 127;
    int h  = (bid >> 7) & 3;
    int b  = bid >> 9;
    int bh = b*4 + h;
    int pos0 = b*HW + c*Q;
    int tid = threadIdx.x;
    int tx = tid & 15, ty = tid >> 4;

    if (tid < Q) sPt[tid] = g_P[(size_t)bh*HW + c*Q + tid];
    const float* Hsrc = g_hst + ((size_t)bh*NCHUNK + c)*HD*DS;
    for (int idx = tid; idx < 64*64; idx += 256) {
        int p = idx >> 6, n = idx & 63;
        sH[p*68 + n] = Hsrc[p*DS + n];
    }
    __syncthreads();
    for (int idx = tid; idx < Q*64; idx += 256) {
        int t = idx >> 6, n = idx & 63;
        sCw[t*68 + n] = g_xbc[(size_t)(pos0+t)*CC + DI + DS + n] * sPt[t];
    }
    __syncthreads();

    float acc[2][4] = {};
#pragma unroll 4
    for (int k0 = 0; k0 < 64; k0 += 4) {
        float4 a0 = *(const float4*)&sCw[(ty*2+0)*68 + k0];
        float4 a1 = *(const float4*)&sCw[(ty*2+1)*68 + k0];
#pragma unroll
        for (int j = 0; j < 4; j++) {
            float4 hv = *(const float4*)&sH[(tx*4+j)*68 + k0];
            acc[0][j] += a0.x*hv.x + a0.y*hv.y + a0.z*hv.z + a0.w*hv.w;
            acc[1][j] += a1.x*hv.x + a1.y*hv.y + a1.z*hv.z + a1.w*hv.w;
        }
    }
#pragma unroll
    for (int i = 0; i < 2; i++) {
        int t = ty*2+i;
        float* yo = &g_y[(size_t)(pos0+t)*DI + h*HD + tx*4];
        float4 cur = *(float4*)yo;
        cur.x += acc[i][0]; cur.y += acc[i][1]; cur.z += acc[i][2]; cur.w += acc[i][3];
        *(float4*)yo = cur;
    }
}

// ---------------- 5. D-skip + gate(silu(z)) + RMSNorm ---------------------
__global__ void gate_kernel(const float* __restrict__ Dsk, const float* __restrict__ rmsw) {
    int warp = threadIdx.x >> 5, lane = threadIdx.x & 31;
    int pos = blockIdx.x * 8 + warp;
    const float* zrow  = g_zx  + (size_t)pos*DINP;
    const float* xrow  = g_xbc + (size_t)pos*CC;
    const float* yrow  = g_y   + (size_t)pos*DI;
    float gv[8]; float ss = 0.f;
#pragma unroll
    for (int i = 0; i < 8; i++) {
        int cc = lane + 32*i; int h = cc >> 6;
        float y = yrow[cc] + Dsk[h]*xrow[cc];
        float z = zrow[cc];
        float g = y * (z / (1.f + expf(-z)));
        gv[i] = g; ss += g*g;
    }
#pragma unroll
    for (int o = 16; o > 0; o >>= 1) ss += __shfl_xor_sync(0xffffffffu, ss, o);
    float sc = rsqrtf(ss*(1.f/256.f) + 1e-5f);
#pragma unroll
    for (int i = 0; i < 8; i++) {
        int cc = lane + 32*i;
        g_gate[(size_t)pos*DI + cc] = gv[i]*sc*rmsw[cc];
    }
}

// ---------------- 6. out_proj GEMM + residual + transpose to (b,c,h,w) ----
__global__ void gemm_out(const float* __restrict__ W, const float* __restrict__ noisy) {
    __shared__ float As[16][64];
    __shared__ float Ws[16][68];
    __shared__ float sOut[64][65];
    int bm = blockIdx.y * 64, bn = blockIdx.x * 64;
    int tx = threadIdx.x & 15, ty = threadIdx.x >> 4;
    float acc[4][4] = {};
    for (int k0 = 0; k0 < DI; k0 += 16) {
#pragma unroll
        for (int i = 0; i < 4; i++) {
            int t = threadIdx.x + i*256; int m = t >> 4, kk = t & 15;
            As[kk][m] = g_gate[(size_t)(bm+m)*DI + k0 + kk];
        }
#pragma unroll
        for (int i = 0; i < 4; i++) {
            int t = threadIdx.x + i*256; int n = t >> 4, kk = t & 15;
            Ws[kk][n] = W[(size_t)(bn+n)*DI + k0 + kk];
        }
        __syncthreads();
#pragma unroll
        for (int kk = 0; kk < 16; kk++) {
            float a[4], wv[4];
#pragma unroll
            for (int i = 0; i < 4; i++) { a[i] = As[kk][ty*4+i]; wv[i] = Ws[kk][tx*4+i]; }
#pragma unroll
            for (int i = 0; i < 4; i++)
#pragma unroll
                for (int j = 0; j < 4; j++) acc[i][j] += a[i]*wv[j];
        }
        __syncthreads();
    }
#pragma unroll
    for (int i = 0; i < 4; i++)
#pragma unroll
        for (int j = 0; j < 4; j++) sOut[tx*4+j][ty*4+i] = acc[i][j];
    __syncthreads();
    for (int r = 0; r < 16; r++) {
        int nl = r*4 + (threadIdx.x >> 6), ml = threadIdx.x & 63;
        int pos = bm + ml, c = bn + nl;
        int b = pos >> 12, sp = pos & 4095;
        size_t o = ((size_t)(b*CH + c))*HW + sp;
        g_res[o] = noisy[o] + sOut[nl][ml];
    }
}

// ---------------- 7/8. 3x3 conv (reflect pad) + ReLU [+ residual to out] ---
__global__ void conv3_kernel(const float* __restrict__ in, const float* __restrict__ w,
                             const float* __restrict__ bias, float* __restrict__ out,
                             const float* __restrict__ resid) {
    __shared__ float sIn[16][18][34];
    __shared__ float sW[8][16][9];
    int b = blockIdx.z, co0 = blockIdx.y * 8;
    int bx = blockIdx.x & 1, by = blockIdx.x >> 1;
    int x0 = bx*32, y0 = by*16;
    int x = threadIdx.x & 31, ty = threadIdx.x >> 5;
    float acc[2][8];
#pragma unroll
    for (int px = 0; px < 2; px++)
#pragma unroll
        for (int co = 0; co < 8; co++) acc[px][co] = bias[co0+co];

    for (int ci0 = 0; ci0 < CH; ci0 += 16) {
        for (int idx = threadIdx.x; idx < 16*18*34; idx += 256) {
            int ci = idx / 612; int rem = idx - ci*612;
            int yy = rem / 34;  int xx = rem - yy*34;
            int iy = y0 + yy - 1; iy = iy < 0 ? -iy : (iy >= 64 ? 126 - iy : iy);
            int ix = x0 + xx - 1; ix = ix < 0 ? -ix : (ix >= 64 ? 126 - ix : ix);
            sIn[ci][yy][xx] = in[(((size_t)b*CH + ci0 + ci)*64 + iy)*64 + ix];
        }
        for (int idx = threadIdx.x; idx < 8*16*9; idx += 256) {
            int co = idx / 144; int rem = idx - co*144;
            int ci = rem / 9;   int k = rem - ci*9;
            sW[co][ci][k] = w[((size_t)(co0+co)*CH + ci0 + ci)*9 + k];
        }
        __syncthreads();
#pragma unroll 1
        for (int ci = 0; ci < 16; ci++) {
#pragma unroll
            for (int ky = 0; ky < 3; ky++)
#pragma unroll
                for (int kx = 0; kx < 3; kx++) {
                    float v0 = sIn[ci][ty   + ky][x + kx];
                    float v1 = sIn[ci][ty+8 + ky][x + kx];
#pragma unroll
                    for (int co = 0; co < 8; co++) {
                        float wv = sW[co][ci][ky*3 + kx];
                        acc[0][co] += v0*wv;
                        acc[1][co] += v1*wv;
                    }
                }
        }
        __syncthreads();
    }
#pragma unroll
    for (int px = 0; px < 2; px++)
#pragma unroll
        for (int co = 0; co < 8; co++) {
            float v = fmaxf(acc[px][co], 0.f);
            size_t o = (((size_t)b*CH + co0 + co)*64 + y0 + ty + px*8)*64 + x0 + x;
            out[o] = resid ? resid[o] + v : v;
        }
}

// ---------------- launch ---------------------------------------------------
extern "C" void kernel_launch(void* const* d_in, const int* in_sizes, int n_in,
                              void* d_out, int out_size) {
    const float* noisy = (const float*)d_in[0];
    const float* aux   = (const float*)d_in[1];
    const float* gamma = (const float*)d_in[2];
    const float* beta  = (const float*)d_in[3];
    const float* inw   = (const float*)d_in[4];
    const float* cw    = (const float*)d_in[5];
    const float* cb    = (const float*)d_in[6];
    const float* alog  = (const float*)d_in[7];
    const float* dtb   = (const float*)d_in[8];
    const float* Dsk   = (const float*)d_in[9];
    const float* rmsw  = (const float*)d_in[10];
    const float* outw  = (const float*)d_in[11];
    const float* fw1   = (const float*)d_in[12];
    const float* fb1   = (const float*)d_in[13];
    const float* fw2   = (const float*)d_in[14];
    const float* fb2   = (const float*)d_in[15];
    float* out = (float*)d_out;

    void *p_res, *p_ff1;
    cudaGetSymbolAddress(&p_res, g_res);
    cudaGetSymbolAddress(&p_ff1, g_ff1);

    ln_kernel<<<2048, 256>>>(noisy, gamma, beta);
    gemm_inproj<<<dim3(11, 256), 256>>>(inw);
    conv1d_kernel<<<dim3(64, 3, 4), 256>>>(cw, cb);
    ssd_chunk<<<2048, 256>>>(alog, dtb);
    ssd_chain<<<64, 1024>>>();
    ssd_inter<<<2048, 256>>>();
    gate_kernel<<<2048, 256>>>(Dsk, rmsw);
    gemm_out<<<dim3(2, 256), 256>>>(outw, noisy);
    conv3_kernel<<<dim3(8, 16, 4), 256>>>((const float*)p_res, fw1, fb1, (float*)p_ff1, nullptr);
    conv3_kernel<<<dim3(8, 16, 4), 256>>>((const float*)p_ff1, fw2, fb2, out, (const float*)p_res);

    // aux passthrough: second half of output
    if (out_size >= 2*LPOS*CH) {
        cudaMemcpyAsync(out + (size_t)LPOS*CH, aux, (size_t)LPOS*CH*sizeof(float),
                        cudaMemcpyDeviceToDevice, 0);
    }
}

// round 3
// speedup vs baseline: 4.9380x; 1.1342x over previous
#include <cuda_runtime.h>
#include <math.h>

#define BB 4
#define CH 128
#define HW 4096
#define LPOS (BB*HW)     // 16384 positions total
#define DINP 644
#define DI 256
#define NH 4
#define HD 64
#define DS 64
#define CC 384
#define Q 32             // SSD chunk length
#define NCHUNK (HW/Q)    // 128 chunks per (b)

typedef unsigned long long ull;

__device__ __forceinline__ void ffma2(ull& d, ull a, ull b) {
    asm("fma.rn.f32x2 %0, %1, %2, %0;" : "+l"(d) : "l"(a), "l"(b));
}
__device__ __forceinline__ float ullsum(ull v) {
    float lo, hi;
    asm("mov.b64 {%0,%1}, %2;" : "=f"(lo), "=f"(hi) : "l"(v));
    return lo + hi;
}

// ---------------- scratch (device globals; no allocation allowed) ----------
__device__ float g_normed[(size_t)LPOS*CH];          // 8.4 MB
__device__ float g_zx[(size_t)LPOS*DINP];            // 42 MB
__device__ float g_xbc[(size_t)LPOS*CC];             // 25 MB
__device__ float g_y[(size_t)LPOS*DI];               // 16.8 MB (scan output)
__device__ float g_U[(size_t)16*NCHUNK*HD*DS];       // 33.5 MB chunk outer sums
__device__ float g_hst[(size_t)16*NCHUNK*HD*DS];     // 33.5 MB chunk start states
__device__ float g_P[(size_t)16*HW];                 // exp(S_t) per (bh,pos)
__device__ float g_D[16*NCHUNK];                     // chunk decay
__device__ float g_gate[(size_t)LPOS*DI];            // 16.8 MB
__device__ float g_res[(size_t)LPOS*CH];             // 8.4 MB
__device__ float g_ff1[(size_t)LPOS*CH];             // 8.4 MB

// ---------------- 1. LayerNorm over channels (transposed gather) ----------
__global__ void ln_kernel(const float* __restrict__ noisy,
                          const float* __restrict__ gamma,
                          const float* __restrict__ beta) {
    int warp = threadIdx.x >> 5, lane = threadIdx.x & 31;
    int pos = blockIdx.x * 8 + warp;            // 0..16383
    int b = pos >> 12, sp = pos & 4095;
    const float* src = noisy + (size_t)b*CH*HW + sp;
    float v[4]; float s = 0.f, s2 = 0.f;
#pragma unroll
    for (int i = 0; i < 4; i++) {
        int c = lane + 32*i;
        v[i] = src[(size_t)c*HW];
        s += v[i]; s2 += v[i]*v[i];
    }
#pragma unroll
    for (int o = 16; o > 0; o >>= 1) {
        s  += __shfl_xor_sync(0xffffffffu, s,  o);
        s2 += __shfl_xor_sync(0xffffffffu, s2, o);
    }
    float mean = s * (1.f/128.f);
    float var  = s2 * (1.f/128.f) - mean*mean;
    float inv  = rsqrtf(var + 1e-5f);
#pragma unroll
    for (int i = 0; i < 4; i++) {
        int c = lane + 32*i;
        g_normed[(size_t)pos*CH + c] = (v[i]-mean)*inv*gamma[c] + beta[c];
    }
}

// ---------------- 2. in_proj GEMM (f32x2): (16384x128)@(644x128)^T --------
// Block tile 128m x 128n, k packed in pairs (64 pairs). 256 threads,
// 8x8 strided thread tile (m = ty+16i, n = tx+16j). FFMA2 accumulators hold
// (even-k partial, odd-k partial); summed in epilogue.
__global__ void __launch_bounds__(256) gemm_inproj(const float* __restrict__ W) {
    __shared__ ull As[16][129];
    __shared__ ull Ws[16][129];
    int bm = blockIdx.y * 128, bn = blockIdx.x * 128;
    int tid = threadIdx.x;
    int tx = tid & 15, ty = tid >> 4;
    ull acc[8][8];
#pragma unroll
    for (int i = 0; i < 8; i++)
#pragma unroll
        for (int j = 0; j < 8; j++) acc[i][j] = 0ull;

    for (int k0 = 0; k0 < CH; k0 += 32) {
#pragma unroll
        for (int v = 0; v < 4; v++) {
            int gidx = tid + v*256;             // 0..1023
            int kp2 = gidx & 7, m = gidx >> 3;
            ulonglong2 d = *(const ulonglong2*)&g_normed[(size_t)(bm+m)*CH + k0 + kp2*4];
            As[2*kp2][m]   = d.x;
            As[2*kp2+1][m] = d.y;
        }
#pragma unroll
        for (int v = 0; v < 4; v++) {
            int gidx = tid + v*256;
            int kp2 = gidx & 7, n = gidx >> 3;
            ulonglong2 d;
            if (bn + n < DINP) d = *(const ulonglong2*)&W[(size_t)(bn+n)*CH + k0 + kp2*4];
            else { d.x = 0ull; d.y = 0ull; }
            Ws[2*kp2][n]   = d.x;
            Ws[2*kp2+1][n] = d.y;
        }
        __syncthreads();
#pragma unroll
        for (int kp = 0; kp < 16; kp++) {
            ull a[8], w[8];
#pragma unroll
            for (int i = 0; i < 8; i++) a[i] = As[kp][ty + 16*i];
#pragma unroll
            for (int j = 0; j < 8; j++) w[j] = Ws[kp][tx + 16*j];
#pragma unroll
            for (int i = 0; i < 8; i++)
#pragma unroll
                for (int j = 0; j < 8; j++) ffma2(acc[i][j], a[i], w[j]);
        }
        __syncthreads();
    }
#pragma unroll
    for (int i = 0; i < 8; i++) {
        int row = bm + ty + 16*i;
#pragma unroll
        for (int j = 0; j < 8; j++) {
            int col = bn + tx + 16*j;
            if (col < DINP) g_zx[(size_t)row*DINP + col] = ullsum(acc[i][j]);
        }
    }
}

// ---------------- 3. causal depthwise conv1d (k=5) + bias + SiLU ----------
__global__ void conv1d_kernel(const float* __restrict__ cw, const float* __restrict__ cb) {
    __shared__ float s[68][128];
    int b = blockIdx.z, ct = blockIdx.y * 128, p0 = blockIdx.x * 64;
    const float* zxb = g_zx + (size_t)b*HW*DINP;
    for (int idx = threadIdx.x; idx < 68*128; idx += 256) {
        int r = idx >> 7, c = idx & 127;
        int pos = p0 - 4 + r;
        s[r][c] = (pos >= 0) ? zxb[(size_t)pos*DINP + DI + ct + c] : 0.f;
    }
    __syncthreads();
    for (int idx = threadIdx.x; idx < 64*128; idx += 256) {
        int r = idx >> 7, c = idx & 127;
        int ch = ct + c;
        float acc = cb[ch];
#pragma unroll
        for (int k = 0; k < 5; k++) acc += s[r+k][c] * cw[ch*5 + k];
        float o = acc / (1.f + expf(-acc));
        g_xbc[((size_t)b*HW + p0 + r)*CC + ch] = o;
    }
}

// ---------------- 4a. SSD chunk kernel ------------------------------------
__global__ void __launch_bounds__(256) ssd_chunk(const float* __restrict__ Alog,
                                                 const float* __restrict__ dtb) {
    __shared__ float sX[Q*64];        // [s][p]  stride 64
    __shared__ float sB[Q*68];        // [s][n]  stride 68 (later scaled by wU)
    __shared__ float sC[Q*68];        // [s][n]; reused as Ms[s][t] stride 33
    __shared__ float sdt[Q], sS[Q], sWU[Q];

    int bid = blockIdx.x;
    int c  = bid & 127;
    int h  = (bid >> 7) & 3;
    int b  = bid >> 9;
    int bh = b*4 + h;
    int pos0 = b*HW + c*Q;
    int tid = threadIdx.x;
    int tx = tid & 15, ty = tid >> 4;

    if (tid < Q) {
        float raw = g_zx[(size_t)(pos0+tid)*DINP + 640 + h] + dtb[h];
        float dt = (raw > 20.f) ? raw : log1pf(expf(raw));
        sdt[tid] = dt;
    }
    for (int idx = tid; idx < Q*64; idx += 256) {
        int s = idx >> 6, n = idx & 63;
        const float* row = g_xbc + (size_t)(pos0+s)*CC;
        sX[s*64 + n] = row[h*HD + n];
        sB[s*68 + n] = row[DI + n];
        sC[s*68 + n] = row[DI + DS + n];
    }
    __syncthreads();
    if (tid == 0) {
        float Ah = -expf(Alog[h]);
        float run = 0.f;
#pragma unroll
        for (int s = 0; s < Q; s++) { run += sdt[s]*Ah; sS[s] = run; }
    }
    __syncthreads();
    float Stot = sS[Q-1];
    if (tid < Q) {
        sWU[tid] = expf(Stot - sS[tid]) * sdt[tid];
        g_P[(size_t)bh*HW + c*Q + tid] = expf(sS[tid]);
        if (tid == 0) g_D[bh*NCHUNK + c] = expf(Stot);
    }
    __syncthreads();

    float mac[2][2] = {};
#pragma unroll 4
    for (int k0 = 0; k0 < 64; k0 += 4) {
        float4 a0 = *(const float4*)&sC[(ty*2+0)*68 + k0];
        float4 a1 = *(const float4*)&sC[(ty*2+1)*68 + k0];
        float4 b0 = *(const float4*)&sB[(tx*2+0)*68 + k0];
        float4 b1 = *(const float4*)&sB[(tx*2+1)*68 + k0];
        mac[0][0] += a0.x*b0.x + a0.y*b0.y + a0.z*b0.z + a0.w*b0.w;
        mac[0][1] += a0.x*b1.x + a0.y*b1.y + a0.z*b1.z + a0.w*b1.w;
        mac[1][0] += a1.x*b0.x + a1.y*b0.y + a1.z*b0.z + a1.w*b0.w;
        mac[1][1] += a1.x*b1.x + a1.y*b1.y + a1.z*b1.z + a1.w*b1.w;
    }
    __syncthreads();
    float* sMs = sC;
#pragma unroll
    for (int i = 0; i < 2; i++)
#pragma unroll
        for (int j = 0; j < 2; j++) {
            int t = ty*2+i, s = tx*2+j;
            float wgt = (s <= t) ? expf(sS[t]-sS[s])*sdt[s] : 0.f;
            sMs[s*33 + t] = mac[i][j]*wgt;
        }
    for (int idx = tid; idx < Q*64; idx += 256) {
        int s = idx >> 6, n = idx & 63;
        sB[s*68 + n] *= sWU[s];
    }
    __syncthreads();

    {
        float acc[2][4] = {};
#pragma unroll 4
        for (int s = 0; s < Q; s++) {
            float m0 = sMs[s*33 + ty*2+0];
            float m1 = sMs[s*33 + ty*2+1];
            float4 xv = *(const float4*)&sX[s*64 + tx*4];
            acc[0][0] += m0*xv.x; acc[0][1] += m0*xv.y; acc[0][2] += m0*xv.z; acc[0][3] += m0*xv.w;
            acc[1][0] += m1*xv.x; acc[1][1] += m1*xv.y; acc[1][2] += m1*xv.z; acc[1][3] += m1*xv.w;
        }
#pragma unroll
        for (int i = 0; i < 2; i++) {
            int t = ty*2+i;
            float4 o; o.x = acc[i][0]; o.y = acc[i][1]; o.z = acc[i][2]; o.w = acc[i][3];
            *(float4*)&g_y[(size_t)(pos0+t)*DI + h*HD + tx*4] = o;
        }
    }

    {
        float acc[4][4] = {};
#pragma unroll 4
        for (int s = 0; s < Q; s++) {
            float4 av = *(const float4*)&sX[s*64 + ty*4];
            float4 bv = *(const float4*)&sB[s*68 + tx*4];
            float a[4] = {av.x, av.y, av.z, av.w};
            float bb[4] = {bv.x, bv.y, bv.z, bv.w};
#pragma unroll
            for (int i = 0; i < 4; i++)
#pragma unroll
                for (int j = 0; j < 4; j++) acc[i][j] += a[i]*bb[j];
        }
        float* Uo = g_U + ((size_t)bh*NCHUNK + c)*HD*DS;
#pragma unroll
        for (int i = 0; i < 4; i++) {
            int p = ty*4+i;
            float4 o; o.x = acc[i][0]; o.y = acc[i][1]; o.z = acc[i][2]; o.w = acc[i][3];
            *(float4*)&Uo[p*DS + tx*4] = o;
        }
    }
}

// ---------------- 4b. chunk-state recurrence ------------------------------
__global__ void ssd_chain() {
    int e = blockIdx.x*1024 + threadIdx.x;
    int bh = e >> 12, el = e & 4095;
    const float* U = g_U   + (size_t)bh*NCHUNK*4096 + el;
    float*       H = g_hst + (size_t)bh*NCHUNK*4096 + el;
    const float* Dd = g_D + bh*NCHUNK;
    float hval = 0.f;
    float u = U[0], d = Dd[0];
    for (int ci = 0; ci < NCHUNK; ci++) {
        float un = 0.f, dn = 0.f;
        if (ci + 1 < NCHUNK) { un = U[(size_t)(ci+1)*4096]; dn = Dd[ci+1]; }
        H[(size_t)ci*4096] = hval;
        hval = d*hval + u;
        u = un; d = dn;
    }
}

// ---------------- 4c. inter-chunk output ----------------------------------
__global__ void __launch_bounds__(256) ssd_inter() {
    __shared__ float sH[64*68];
    __shared__ float sCw[Q*68];
    __shared__ float sPt[Q];
    int bid = blockIdx.x;
    int c  = bid & 127;
    int h  = (bid >> 7) & 3;
    int b  = bid >> 9;
    int bh = b*4 + h;
    int pos0 = b*HW + c*Q;
    int tid = threadIdx.x;
    int tx = tid & 15, ty = tid >> 4;

    if (tid < Q) sPt[tid] = g_P[(size_t)bh*HW + c*Q + tid];
    const float* Hsrc = g_hst + ((size_t)bh*NCHUNK + c)*HD*DS;
    for (int idx = tid; idx < 64*64; idx += 256) {
        int p = idx >> 6, n = idx & 63;
        sH[p*68 + n] = Hsrc[p*DS + n];
    }
    __syncthreads();
    for (int idx = tid; idx < Q*64; idx += 256) {
        int t = idx >> 6, n = idx & 63;
        sCw[t*68 + n] = g_xbc[(size_t)(pos0+t)*CC + DI + DS + n] * sPt[t];
    }
    __syncthreads();

    float acc[2][4] = {};
#pragma unroll 4
    for (int k0 = 0; k0 < 64; k0 += 4) {
        float4 a0 = *(const float4*)&sCw[(ty*2+0)*68 + k0];
        float4 a1 = *(const float4*)&sCw[(ty*2+1)*68 + k0];
#pragma unroll
        for (int j = 0; j < 4; j++) {
            float4 hv = *(const float4*)&sH[(tx*4+j)*68 + k0];
            acc[0][j] += a0.x*hv.x + a0.y*hv.y + a0.z*hv.z + a0.w*hv.w;
            acc[1][j] += a1.x*hv.x + a1.y*hv.y + a1.z*hv.z + a1.w*hv.w;
        }
    }
#pragma unroll
    for (int i = 0; i < 2; i++) {
        int t = ty*2+i;
        float* yo = &g_y[(size_t)(pos0+t)*DI + h*HD + tx*4];
        float4 cur = *(float4*)yo;
        cur.x += acc[i][0]; cur.y += acc[i][1]; cur.z += acc[i][2]; cur.w += acc[i][3];
        *(float4*)yo = cur;
    }
}

// ---------------- 5. D-skip + gate(silu(z)) + RMSNorm ---------------------
__global__ void gate_kernel(const float* __restrict__ Dsk, const float* __restrict__ rmsw) {
    int warp = threadIdx.x >> 5, lane = threadIdx.x & 31;
    int pos = blockIdx.x * 8 + warp;
    const float* zrow  = g_zx  + (size_t)pos*DINP;
    const float* xrow  = g_xbc + (size_t)pos*CC;
    const float* yrow  = g_y   + (size_t)pos*DI;
    float gv[8]; float ss = 0.f;
#pragma unroll
    for (int i = 0; i < 8; i++) {
        int cc = lane + 32*i; int h = cc >> 6;
        float y = yrow[cc] + Dsk[h]*xrow[cc];
        float z = zrow[cc];
        float g = y * (z / (1.f + expf(-z)));
        gv[i] = g; ss += g*g;
    }
#pragma unroll
    for (int o = 16; o > 0; o >>= 1) ss += __shfl_xor_sync(0xffffffffu, ss, o);
    float sc = rsqrtf(ss*(1.f/256.f) + 1e-5f);
#pragma unroll
    for (int i = 0; i < 8; i++) {
        int cc = lane + 32*i;
        g_gate[(size_t)pos*DI + cc] = gv[i]*sc*rmsw[cc];
    }
}

// ---------------- 6. out_proj GEMM (f32x2) + residual + transpose ---------
// M=16384, N=128 (one n-block), K=256. Same engine as gemm_inproj.
// Epilogue stages a 16n x 128m transpose tile through smem for coalesced
// (b,c,sp) stores with the residual add.
__global__ void __launch_bounds__(256) gemm_out(const float* __restrict__ W,
                                                const float* __restrict__ noisy) {
    __shared__ ull As[16][129];
    __shared__ ull Ws[16][129];
    int bm = blockIdx.x * 128;
    int tid = threadIdx.x;
    int tx = tid & 15, ty = tid >> 4;
    ull acc[8][8];
#pragma unroll
    for (int i = 0; i < 8; i++)
#pragma unroll
        for (int j = 0; j < 8; j++) acc[i][j] = 0ull;

    for (int k0 = 0; k0 < DI; k0 += 32) {
#pragma unroll
        for (int v = 0; v < 4; v++) {
            int gidx = tid + v*256;
            int kp2 = gidx & 7, m = gidx >> 3;
            ulonglong2 d = *(const ulonglong2*)&g_gate[(size_t)(bm+m)*DI + k0 + kp2*4];
            As[2*kp2][m]   = d.x;
            As[2*kp2+1][m] = d.y;
        }
#pragma unroll
        for (int v = 0; v < 4; v++) {
            int gidx = tid + v*256;
            int kp2 = gidx & 7, n = gidx >> 3;
            ulonglong2 d = *(const ulonglong2*)&W[(size_t)n*DI + k0 + kp2*4];
            Ws[2*kp2][n]   = d.x;
            Ws[2*kp2+1][n] = d.y;
        }
        __syncthreads();
#pragma unroll
        for (int kp = 0; kp < 16; kp++) {
            ull a[8], w[8];
#pragma unroll
            for (int i = 0; i < 8; i++) a[i] = As[kp][ty + 16*i];
#pragma unroll
            for (int j = 0; j < 8; j++) w[j] = Ws[kp][tx + 16*j];
#pragma unroll
            for (int i = 0; i < 8; i++)
#pragma unroll
                for (int j = 0; j < 8; j++) ffma2(acc[i][j], a[i], w[j]);
        }
        __syncthreads();
    }

    // staged transpose epilogue, 8 chunks of 16 channels
    float* T = (float*)&As[0][0];     // 16 x 130 floats = 8.3KB, fits in As
    int b = bm >> 12, sp0 = bm & 4095;
    for (int j = 0; j < 8; j++) {
#pragma unroll
        for (int i = 0; i < 8; i++)
            T[tx*130 + ty + 16*i] = ullsum(acc[i][j]);
        __syncthreads();
#pragma unroll
        for (int r = 0; r < 8; r++) {
            int ridx = tid + r*256;
            int cl = ridx >> 7, mm = ridx & 127;
            int c = cl + 16*j;
            size_t o = ((size_t)(b*CH + c))*HW + sp0 + mm;
            g_res[o] = noisy[o] + T[cl*130 + mm];
        }
        __syncthreads();
    }
}

// ---------------- 7/8. 3x3 conv (f32x2 over ci-pairs) + ReLU --------------
// 128 threads: xg = tid&7 (8 px each in x), yy = tid>>3 (16 rows).
// Block tile: 64x16 spatial, 8 output channels. ci processed in pairs packed
// into f32x2 lanes; weights resident in smem for the whole block.
__global__ void __launch_bounds__(128) conv3_kernel(const float* __restrict__ in,
                                                    const float* __restrict__ w,
                                                    const float* __restrict__ bias,
                                                    float* __restrict__ out,
                                                    const float* __restrict__ resid) {
    __shared__ float sW[64*9*8*2];       // [cp][k][co][parity] 36.9KB
    __shared__ float sIn[18*132];        // [yy][xx-pair *2] 9.5KB, pitch 132 floats

    int b = blockIdx.z, co0 = blockIdx.y * 8, y0 = blockIdx.x * 16;
    int tid = threadIdx.x;
    int xg = tid & 7, yy0 = tid >> 3;
    int x0 = xg * 8;

    // load all weights once: gmem [co][ci][k] -> smem [cp][k][co][parity]
    for (int idx = tid; idx < 8*CH*9; idx += 128) {
        int co = idx / (CH*9);
        int r  = idx - co*CH*9;
        int ci = r / 9, k = r - ci*9;
        sW[((ci >> 1)*9 + k)*16 + co*2 + (ci & 1)] = w[((size_t)(co0+co)*CH + ci)*9 + k];
    }

    ull acc[8][8];
#pragma unroll
    for (int px = 0; px < 8; px++)
#pragma unroll
        for (int co = 0; co < 8; co++) acc[px][co] = 0ull;

    for (int cp = 0; cp < 64; cp++) {
        __syncthreads();
        // load 2 input planes (ci = 2cp, 2cp+1) with reflect halo, interleaved
#pragma unroll
        for (int p = 0; p < 2; p++) {
            const float* plane = in + ((size_t)b*CH + 2*cp + p)*64*64;
            for (int idx = tid; idx < 18*66; idx += 128) {
                int yv = idx / 66, xx = idx - yv*66;
                int iy = y0 + yv - 1; iy = iy < 0 ? -iy : (iy >= 64 ? 126 - iy : iy);
                int ix = xx - 1;      ix = ix < 0 ? -ix : (ix >= 64 ? 126 - ix : ix);
                sIn[yv*132 + xx*2 + p] = plane[iy*64 + ix];
            }
        }
        __syncthreads();

#pragma unroll
        for (int ky = 0; ky < 3; ky++) {
            const ulonglong2* vp = (const ulonglong2*)&sIn[(yy0 + ky)*132 + x0*2];
            ull v[10];
#pragma unroll
            for (int q = 0; q < 5; q++) {
                ulonglong2 d = vp[q];
                v[2*q] = d.x; v[2*q+1] = d.y;
            }
#pragma unroll
            for (int kx = 0; kx < 3; kx++) {
                const ull* wrow = (const ull*)&sW[((cp*9 + ky*3 + kx))*16];
#pragma unroll
                for (int co = 0; co < 8; co++) {
                    ull w2 = wrow[co];
#pragma unroll
                    for (int px = 0; px < 8; px++)
                        ffma2(acc[px][co], v[px + kx], w2);
                }
            }
        }
    }

    // epilogue: sum pair lanes, bias, relu, optional residual; float4 stores
#pragma unroll
    for (int co = 0; co < 8; co++) {
        float bv = bias[co0 + co];
        float r0[8];
#pragma unroll
        for (int px = 0; px < 8; px++)
            r0[px] = fmaxf(ullsum(acc[px][co]) + bv, 0.f);
        size_t o = (((size_t)b*CH + co0 + co)*64 + y0 + yy0)*64 + x0;
        if (resid) {
#pragma unroll
            for (int px = 0; px < 8; px++) r0[px] += resid[o + px];
        }
        float4 lo = make_float4(r0[0], r0[1], r0[2], r0[3]);
        float4 hi = make_float4(r0[4], r0[5], r0[6], r0[7]);
        *(float4*)&out[o]     = lo;
        *(float4*)&out[o + 4] = hi;
    }
}

// ---------------- launch ---------------------------------------------------
extern "C" void kernel_launch(void* const* d_in, const int* in_sizes, int n_in,
                              void* d_out, int out_size) {
    const float* noisy = (const float*)d_in[0];
    const float* aux   = (const float*)d_in[1];
    const float* gamma = (const float*)d_in[2];
    const float* beta  = (const float*)d_in[3];
    const float* inw   = (const float*)d_in[4];
    const float* cw    = (const float*)d_in[5];
    const float* cb    = (const float*)d_in[6];
    const float* alog  = (const float*)d_in[7];
    const float* dtb   = (const float*)d_in[8];
    const float* Dsk   = (const float*)d_in[9];
    const float* rmsw  = (const float*)d_in[10];
    const float* outw  = (const float*)d_in[11];
    const float* fw1   = (const float*)d_in[12];
    const float* fb1   = (const float*)d_in[13];
    const float* fw2   = (const float*)d_in[14];
    const float* fb2   = (const float*)d_in[15];
    float* out = (float*)d_out;

    void *p_res, *p_ff1;
    cudaGetSymbolAddress(&p_res, g_res);
    cudaGetSymbolAddress(&p_ff1, g_ff1);

    ln_kernel<<<2048, 256>>>(noisy, gamma, beta);
    gemm_inproj<<<dim3(6, 128), 256>>>(inw);
    conv1d_kernel<<<dim3(64, 3, 4), 256>>>(cw, cb);
    ssd_chunk<<<2048, 256>>>(alog, dtb);
    ssd_chain<<<64, 1024>>>();
    ssd_inter<<<2048, 256>>>();
    gate_kernel<<<2048, 256>>>(Dsk, rmsw);
    gemm_out<<<128, 256>>>(outw, noisy);
    conv3_kernel<<<dim3(4, 16, 4), 128>>>((const float*)p_res, fw1, fb1, (float*)p_ff1, nullptr);
    conv3_kernel<<<dim3(4, 16, 4), 128>>>((const float*)p_ff1, fw2, fb2, out, (const float*)p_res);

    // aux passthrough: second half of output
    if (out_size >= 2*LPOS*CH) {
        cudaMemcpyAsync(out + (size_t)LPOS*CH, aux, (size_t)LPOS*CH*sizeof(float),
                        cudaMemcpyDeviceToDevice, 0);
    }
}

// round 4
// speedup vs baseline: 7.3163x; 1.4816x over previous
#include <cuda_runtime.h>
#include <math.h>
#include <stdint.h>

#define BB 4
#define CH 128
#define HW 4096
#define LPOS (BB*HW)     // 16384 positions total
#define DINP 644
#define DI 256
#define NH 4
#define HD 64
#define DS 64
#define CC 384
#define Q 32             // SSD chunk length
#define NCHUNK (HW/Q)    // 128 chunks per (b)

typedef unsigned long long ull;

__device__ __forceinline__ void ffma2(ull& d, ull a, ull b) {
    asm("fma.rn.f32x2 %0, %1, %2, %0;" : "+l"(d) : "l"(a), "l"(b));
}
__device__ __forceinline__ float ullsum(ull v) {
    float lo, hi;
    asm("mov.b64 {%0,%1}, %2;" : "=f"(lo), "=f"(hi) : "l"(v));
    return lo + hi;
}
__device__ __forceinline__ float tf32r(float x) {
    uint32_t u;
    asm("cvt.rna.tf32.f32 %0, %1;" : "=r"(u) : "f"(x));
    return __uint_as_float(u);
}
__device__ __forceinline__ void mma_tf32(float* d, const uint32_t* a, const uint32_t* b) {
    asm("mma.sync.aligned.m16n8k8.row.col.f32.tf32.tf32.f32 "
        "{%0,%1,%2,%3},{%4,%5,%6,%7},{%8,%9},{%0,%1,%2,%3};"
        : "+f"(d[0]), "+f"(d[1]), "+f"(d[2]), "+f"(d[3])
        : "r"(a[0]), "r"(a[1]), "r"(a[2]), "r"(a[3]), "r"(b[0]), "r"(b[1]));
}

// ---------------- scratch (device globals; no allocation allowed) ----------
__device__ float g_normed[(size_t)LPOS*CH];          // 8.4 MB
__device__ float g_zx[(size_t)LPOS*DINP];            // 42 MB
__device__ float g_xbc[(size_t)LPOS*CC];             // 25 MB
__device__ float g_y[(size_t)LPOS*DI];               // 16.8 MB (scan output)
__device__ float g_U[(size_t)16*NCHUNK*HD*DS];       // 33.5 MB chunk outer sums
__device__ float g_hst[(size_t)16*NCHUNK*HD*DS];     // 33.5 MB chunk start states
__device__ float g_P[(size_t)16*HW];                 // exp(S_t) per (bh,pos)
__device__ float g_D[16*NCHUNK];                     // chunk decay
__device__ float g_gate[(size_t)LPOS*DI];            // 16.8 MB
__device__ float g_res[(size_t)LPOS*CH];             // 8.4 MB
__device__ float g_ff1[(size_t)LPOS*CH];             // 8.4 MB

// ---------------- 1. LayerNorm over channels (transposed gather) ----------
__global__ void ln_kernel(const float* __restrict__ noisy,
                          const float* __restrict__ gamma,
                          const float* __restrict__ beta) {
    int warp = threadIdx.x >> 5, lane = threadIdx.x & 31;
    int pos = blockIdx.x * 8 + warp;            // 0..16383
    int b = pos >> 12, sp = pos & 4095;
    const float* src = noisy + (size_t)b*CH*HW + sp;
    float v[4]; float s = 0.f, s2 = 0.f;
#pragma unroll
    for (int i = 0; i < 4; i++) {
        int c = lane + 32*i;
        v[i] = src[(size_t)c*HW];
        s += v[i]; s2 += v[i]*v[i];
    }
#pragma unroll
    for (int o = 16; o > 0; o >>= 1) {
        s  += __shfl_xor_sync(0xffffffffu, s,  o);
        s2 += __shfl_xor_sync(0xffffffffu, s2, o);
    }
    float mean = s * (1.f/128.f);
    float var  = s2 * (1.f/128.f) - mean*mean;
    float inv  = rsqrtf(var + 1e-5f);
#pragma unroll
    for (int i = 0; i < 4; i++) {
        int c = lane + 32*i;
        g_normed[(size_t)pos*CH + c] = (v[i]-mean)*inv*gamma[c] + beta[c];
    }
}

// ---------------- 2. in_proj GEMM (f32x2): (16384x128)@(644x128)^T --------
__global__ void __launch_bounds__(256) gemm_inproj(const float* __restrict__ W) {
    __shared__ ull As[16][129];
    __shared__ ull Ws[16][129];
    int bm = blockIdx.y * 128, bn = blockIdx.x * 128;
    int tid = threadIdx.x;
    int tx = tid & 15, ty = tid >> 4;
    ull acc[8][8];
#pragma unroll
    for (int i = 0; i < 8; i++)
#pragma unroll
        for (int j = 0; j < 8; j++) acc[i][j] = 0ull;

    for (int k0 = 0; k0 < CH; k0 += 32) {
#pragma unroll
        for (int v = 0; v < 4; v++) {
            int gidx = tid + v*256;             // 0..1023
            int kp2 = gidx & 7, m = gidx >> 3;
            ulonglong2 d = *(const ulonglong2*)&g_normed[(size_t)(bm+m)*CH + k0 + kp2*4];
            As[2*kp2][m]   = d.x;
            As[2*kp2+1][m] = d.y;
        }
#pragma unroll
        for (int v = 0; v < 4; v++) {
            int gidx = tid + v*256;
            int kp2 = gidx & 7, n = gidx >> 3;
            ulonglong2 d;
            if (bn + n < DINP) d = *(const ulonglong2*)&W[(size_t)(bn+n)*CH + k0 + kp2*4];
            else { d.x = 0ull; d.y = 0ull; }
            Ws[2*kp2][n]   = d.x;
            Ws[2*kp2+1][n] = d.y;
        }
        __syncthreads();
#pragma unroll
        for (int kp = 0; kp < 16; kp++) {
            ull a[8], w[8];
#pragma unroll
            for (int i = 0; i < 8; i++) a[i] = As[kp][ty + 16*i];
#pragma unroll
            for (int j = 0; j < 8; j++) w[j] = Ws[kp][tx + 16*j];
#pragma unroll
            for (int i = 0; i < 8; i++)
#pragma unroll
                for (int j = 0; j < 8; j++) ffma2(acc[i][j], a[i], w[j]);
        }
        __syncthreads();
    }
#pragma unroll
    for (int i = 0; i < 8; i++) {
        int row = bm + ty + 16*i;
#pragma unroll
        for (int j = 0; j < 8; j++) {
            int col = bn + tx + 16*j;
            if (col < DINP) g_zx[(size_t)row*DINP + col] = ullsum(acc[i][j]);
        }
    }
}

// ---------------- 3. causal depthwise conv1d (k=5) + bias + SiLU ----------
__global__ void conv1d_kernel(const float* __restrict__ cw, const float* __restrict__ cb) {
    __shared__ float s[68][128];
    int b = blockIdx.z, ct = blockIdx.y * 128, p0 = blockIdx.x * 64;
    const float* zxb = g_zx + (size_t)b*HW*DINP;
    for (int idx = threadIdx.x; idx < 68*128; idx += 256) {
        int r = idx >> 7, c = idx & 127;
        int pos = p0 - 4 + r;
        s[r][c] = (pos >= 0) ? zxb[(size_t)pos*DINP + DI + ct + c] : 0.f;
    }
    __syncthreads();
    for (int idx = threadIdx.x; idx < 64*128; idx += 256) {
        int r = idx >> 7, c = idx & 127;
        int ch = ct + c;
        float acc = cb[ch];
#pragma unroll
        for (int k = 0; k < 5; k++) acc += s[r+k][c] * cw[ch*5 + k];
        float o = acc / (1.f + expf(-acc));
        g_xbc[((size_t)b*HW + p0 + r)*CC + ch] = o;
    }
}

// ---------------- 4a. SSD chunk kernel ------------------------------------
__global__ void __launch_bounds__(256) ssd_chunk(const float* __restrict__ Alog,
                                                 const float* __restrict__ dtb) {
    __shared__ float sX[Q*64];        // [s][p]  stride 64
    __shared__ float sB[Q*68];        // [s][n]  stride 68 (later scaled by wU)
    __shared__ float sC[Q*68];        // [s][n]; reused as Ms[s][t] stride 33
    __shared__ float sdt[Q], sS[Q], sWU[Q];

    int bid = blockIdx.x;
    int c  = bid & 127;
    int h  = (bid >> 7) & 3;
    int b  = bid >> 9;
    int bh = b*4 + h;
    int pos0 = b*HW + c*Q;
    int tid = threadIdx.x;
    int tx = tid & 15, ty = tid >> 4;

    if (tid < Q) {
        float raw = g_zx[(size_t)(pos0+tid)*DINP + 640 + h] + dtb[h];
        float dt = (raw > 20.f) ? raw : log1pf(expf(raw));
        sdt[tid] = dt;
    }
    for (int idx = tid; idx < Q*64; idx += 256) {
        int s = idx >> 6, n = idx & 63;
        const float* row = g_xbc + (size_t)(pos0+s)*CC;
        sX[s*64 + n] = row[h*HD + n];
        sB[s*68 + n] = row[DI + n];
        sC[s*68 + n] = row[DI + DS + n];
    }
    __syncthreads();
    if (tid == 0) {
        float Ah = -expf(Alog[h]);
        float run = 0.f;
#pragma unroll
        for (int s = 0; s < Q; s++) { run += sdt[s]*Ah; sS[s] = run; }
    }
    __syncthreads();
    float Stot = sS[Q-1];
    if (tid < Q) {
        sWU[tid] = expf(Stot - sS[tid]) * sdt[tid];
        g_P[(size_t)bh*HW + c*Q + tid] = expf(sS[tid]);
        if (tid == 0) g_D[bh*NCHUNK + c] = expf(Stot);
    }
    __syncthreads();

    float mac[2][2] = {};
#pragma unroll 4
    for (int k0 = 0; k0 < 64; k0 += 4) {
        float4 a0 = *(const float4*)&sC[(ty*2+0)*68 + k0];
        float4 a1 = *(const float4*)&sC[(ty*2+1)*68 + k0];
        float4 b0 = *(const float4*)&sB[(tx*2+0)*68 + k0];
        float4 b1 = *(const float4*)&sB[(tx*2+1)*68 + k0];
        mac[0][0] += a0.x*b0.x + a0.y*b0.y + a0.z*b0.z + a0.w*b0.w;
        mac[0][1] += a0.x*b1.x + a0.y*b1.y + a0.z*b1.z + a0.w*b1.w;
        mac[1][0] += a1.x*b0.x + a1.y*b0.y + a1.z*b0.z + a1.w*b0.w;
        mac[1][1] += a1.x*b1.x + a1.y*b1.y + a1.z*b1.z + a1.w*b1.w;
    }
    __syncthreads();
    float* sMs = sC;
#pragma unroll
    for (int i = 0; i < 2; i++)
#pragma unroll
        for (int j = 0; j < 2; j++) {
            int t = ty*2+i, s = tx*2+j;
            float wgt = (s <= t) ? expf(sS[t]-sS[s])*sdt[s] : 0.f;
            sMs[s*33 + t] = mac[i][j]*wgt;
        }
    for (int idx = tid; idx < Q*64; idx += 256) {
        int s = idx >> 6, n = idx & 63;
        sB[s*68 + n] *= sWU[s];
    }
    __syncthreads();

    {
        float acc[2][4] = {};
#pragma unroll 4
        for (int s = 0; s < Q; s++) {
            float m0 = sMs[s*33 + ty*2+0];
            float m1 = sMs[s*33 + ty*2+1];
            float4 xv = *(const float4*)&sX[s*64 + tx*4];
            acc[0][0] += m0*xv.x; acc[0][1] += m0*xv.y; acc[0][2] += m0*xv.z; acc[0][3] += m0*xv.w;
            acc[1][0] += m1*xv.x; acc[1][1] += m1*xv.y; acc[1][2] += m1*xv.z; acc[1][3] += m1*xv.w;
        }
#pragma unroll
        for (int i = 0; i < 2; i++) {
            int t = ty*2+i;
            float4 o; o.x = acc[i][0]; o.y = acc[i][1]; o.z = acc[i][2]; o.w = acc[i][3];
            *(float4*)&g_y[(size_t)(pos0+t)*DI + h*HD + tx*4] = o;
        }
    }

    {
        float acc[4][4] = {};
#pragma unroll 4
        for (int s = 0; s < Q; s++) {
            float4 av = *(const float4*)&sX[s*64 + ty*4];
            float4 bv = *(const float4*)&sB[s*68 + tx*4];
            float a[4] = {av.x, av.y, av.z, av.w};
            float bb[4] = {bv.x, bv.y, bv.z, bv.w};
#pragma unroll
            for (int i = 0; i < 4; i++)
#pragma unroll
                for (int j = 0; j < 4; j++) acc[i][j] += a[i]*bb[j];
        }
        float* Uo = g_U + ((size_t)bh*NCHUNK + c)*HD*DS;
#pragma unroll
        for (int i = 0; i < 4; i++) {
            int p = ty*4+i;
            float4 o; o.x = acc[i][0]; o.y = acc[i][1]; o.z = acc[i][2]; o.w = acc[i][3];
            *(float4*)&Uo[p*DS + tx*4] = o;
        }
    }
}

// ---------------- 4b. chunk-state recurrence ------------------------------
__global__ void ssd_chain() {
    int e = blockIdx.x*1024 + threadIdx.x;
    int bh = e >> 12, el = e & 4095;
    const float* U = g_U   + (size_t)bh*NCHUNK*4096 + el;
    float*       H = g_hst + (size_t)bh*NCHUNK*4096 + el;
    const float* Dd = g_D + bh*NCHUNK;
    float hval = 0.f;
    float u = U[0], d = Dd[0];
    for (int ci = 0; ci < NCHUNK; ci++) {
        float un = 0.f, dn = 0.f;
        if (ci + 1 < NCHUNK) { un = U[(size_t)(ci+1)*4096]; dn = Dd[ci+1]; }
        H[(size_t)ci*4096] = hval;
        hval = d*hval + u;
        u = un; d = dn;
    }
}

// ---------------- 4c. inter-chunk output ----------------------------------
__global__ void __launch_bounds__(256) ssd_inter() {
    __shared__ float sH[64*68];
    __shared__ float sCw[Q*68];
    __shared__ float sPt[Q];
    int bid = blockIdx.x;
    int c  = bid & 127;
    int h  = (bid >> 7) & 3;
    int b  = bid >> 9;
    int bh = b*4 + h;
    int pos0 = b*HW + c*Q;
    int tid = threadIdx.x;
    int tx = tid & 15, ty = tid >> 4;

    if (tid < Q) sPt[tid] = g_P[(size_t)bh*HW + c*Q + tid];
    const float* Hsrc = g_hst + ((size_t)bh*NCHUNK + c)*HD*DS;
    for (int idx = tid; idx < 64*64; idx += 256) {
        int p = idx >> 6, n = idx & 63;
        sH[p*68 + n] = Hsrc[p*DS + n];
    }
    __syncthreads();
    for (int idx = tid; idx < Q*64; idx += 256) {
        int t = idx >> 6, n = idx & 63;
        sCw[t*68 + n] = g_xbc[(size_t)(pos0+t)*CC + DI + DS + n] * sPt[t];
    }
    __syncthreads();

    float acc[2][4] = {};
#pragma unroll 4
    for (int k0 = 0; k0 < 64; k0 += 4) {
        float4 a0 = *(const float4*)&sCw[(ty*2+0)*68 + k0];
        float4 a1 = *(const float4*)&sCw[(ty*2+1)*68 + k0];
#pragma unroll
        for (int j = 0; j < 4; j++) {
            float4 hv = *(const float4*)&sH[(tx*4+j)*68 + k0];
            acc[0][j] += a0.x*hv.x + a0.y*hv.y + a0.z*hv.z + a0.w*hv.w;
            acc[1][j] += a1.x*hv.x + a1.y*hv.y + a1.z*hv.z + a1.w*hv.w;
        }
    }
#pragma unroll
    for (int i = 0; i < 2; i++) {
        int t = ty*2+i;
        float* yo = &g_y[(size_t)(pos0+t)*DI + h*HD + tx*4];
        float4 cur = *(float4*)yo;
        cur.x += acc[i][0]; cur.y += acc[i][1]; cur.z += acc[i][2]; cur.w += acc[i][3];
        *(float4*)yo = cur;
    }
}

// ---------------- 5. D-skip + gate(silu(z)) + RMSNorm ---------------------
__global__ void gate_kernel(const float* __restrict__ Dsk, const float* __restrict__ rmsw) {
    int warp = threadIdx.x >> 5, lane = threadIdx.x & 31;
    int pos = blockIdx.x * 8 + warp;
    const float* zrow  = g_zx  + (size_t)pos*DINP;
    const float* xrow  = g_xbc + (size_t)pos*CC;
    const float* yrow  = g_y   + (size_t)pos*DI;
    float gv[8]; float ss = 0.f;
#pragma unroll
    for (int i = 0; i < 8; i++) {
        int cc = lane + 32*i; int h = cc >> 6;
        float y = yrow[cc] + Dsk[h]*xrow[cc];
        float z = zrow[cc];
        float g = y * (z / (1.f + expf(-z)));
        gv[i] = g; ss += g*g;
    }
#pragma unroll
    for (int o = 16; o > 0; o >>= 1) ss += __shfl_xor_sync(0xffffffffu, ss, o);
    float sc = rsqrtf(ss*(1.f/256.f) + 1e-5f);
#pragma unroll
    for (int i = 0; i < 8; i++) {
        int cc = lane + 32*i;
        g_gate[(size_t)pos*DI + cc] = gv[i]*sc*rmsw[cc];
    }
}

// ---------------- 6. out_proj GEMM (f32x2) + residual + transpose ---------
__global__ void __launch_bounds__(256) gemm_out(const float* __restrict__ W,
                                                const float* __restrict__ noisy) {
    __shared__ ull As[16][129];
    __shared__ ull Ws[16][129];
    int bm = blockIdx.x * 128;
    int tid = threadIdx.x;
    int tx = tid & 15, ty = tid >> 4;
    ull acc[8][8];
#pragma unroll
    for (int i = 0; i < 8; i++)
#pragma unroll
        for (int j = 0; j < 8; j++) acc[i][j] = 0ull;

    for (int k0 = 0; k0 < DI; k0 += 32) {
#pragma unroll
        for (int v = 0; v < 4; v++) {
            int gidx = tid + v*256;
            int kp2 = gidx & 7, m = gidx >> 3;
            ulonglong2 d = *(const ulonglong2*)&g_gate[(size_t)(bm+m)*DI + k0 + kp2*4];
            As[2*kp2][m]   = d.x;
            As[2*kp2+1][m] = d.y;
        }
#pragma unroll
        for (int v = 0; v < 4; v++) {
            int gidx = tid + v*256;
            int kp2 = gidx & 7, n = gidx >> 3;
            ulonglong2 d = *(const ulonglong2*)&W[(size_t)n*DI + k0 + kp2*4];
            Ws[2*kp2][n]   = d.x;
            Ws[2*kp2+1][n] = d.y;
        }
        __syncthreads();
#pragma unroll
        for (int kp = 0; kp < 16; kp++) {
            ull a[8], w[8];
#pragma unroll
            for (int i = 0; i < 8; i++) a[i] = As[kp][ty + 16*i];
#pragma unroll
            for (int j = 0; j < 8; j++) w[j] = Ws[kp][tx + 16*j];
#pragma unroll
            for (int i = 0; i < 8; i++)
#pragma unroll
                for (int j = 0; j < 8; j++) ffma2(acc[i][j], a[i], w[j]);
        }
        __syncthreads();
    }

    // staged transpose epilogue, 8 chunks of 16 channels
    float* T = (float*)&As[0][0];     // 16 x 130 floats, fits in As
    int b = bm >> 12, sp0 = bm & 4095;
    for (int j = 0; j < 8; j++) {
#pragma unroll
        for (int i = 0; i < 8; i++)
            T[tx*130 + ty + 16*i] = ullsum(acc[i][j]);
        __syncthreads();
#pragma unroll
        for (int r = 0; r < 8; r++) {
            int ridx = tid + r*256;
            int cl = ridx >> 7, mm = ridx & 127;
            int c = cl + 16*j;
            size_t o = ((size_t)(b*CH + c))*HW + sp0 + mm;
            g_res[o] = noisy[o] + T[cl*130 + mm];
        }
        __syncthreads();
    }
}

// ---------------- 7/8. 3x3 conv via tf32 mma.sync tensor cores ------------
// Block = 256 threads (8 warps). Tile: 64 co x (2 rows x 64 x = 128 px).
// K = 128 ci x 9 taps, processed as 16 ci-chunks of 8; each tap is a k=8 GEMM
// against a shifted window of the transposed input patch T.
// Warp w: yl = w>>2 (row), xq = w&3 (x quarter). Warp tile: m16 (x) x n64 (co).
__global__ void __launch_bounds__(256) conv3_tc(const float* __restrict__ in,
                                                const float* __restrict__ w,
                                                const float* __restrict__ bias,
                                                float* __restrict__ out,
                                                const float* __restrict__ resid) {
    __shared__ float sT[4*66*12];     // [r][xx][ci8] pad 12 -> 12.7KB
    __shared__ float sW[9*8*72];      // [tap][ci8][co64 pad 72] -> 20.7KB

    int b = blockIdx.z, coh = blockIdx.x * 64, y0 = blockIdx.y * 2;
    int tid = threadIdx.x;
    int wrp = tid >> 5, l = tid & 31;
    int yl = wrp >> 2, xq = wrp & 3;
    int lq = l >> 2, lr = l & 3;      // lq = l/4, lr = l%4

    float acc[8][4];
#pragma unroll
    for (int nt = 0; nt < 8; nt++)
#pragma unroll
        for (int i = 0; i < 4; i++) acc[nt][i] = 0.f;

    for (int cc = 0; cc < 16; cc++) {
        int ci0 = cc * 8;
        __syncthreads();
        // stage T: input patch rows y0-1..y0+2, x -1..64 (reflect), 8 channels
        for (int idx = tid; idx < 4*66*8; idx += 256) {
            int xx = idx % 66;
            int t2 = idx / 66;
            int ci = t2 & 7, r = t2 >> 3;
            int iy = y0 - 1 + r; iy = iy < 0 ? -iy : (iy >= 64 ? 126 - iy : iy);
            int ix = xx - 1;     ix = ix < 0 ? -ix : (ix >= 64 ? 126 - ix : ix);
            sT[(r*66 + xx)*12 + ci] = tf32r(in[(((size_t)b*CH + ci0 + ci)*64 + iy)*64 + ix]);
        }
        // stage W: [tap][ci][co]
        for (int idx = tid; idx < 9*8*64; idx += 256) {
            int co = idx / 72;
            int rem = idx - co*72;
            int ci = rem / 9, kk = rem - ci*9;
            sW[(kk*8 + ci)*72 + co] = tf32r(w[((size_t)(coh+co)*CH + ci0 + ci)*9 + kk]);
        }
        __syncthreads();

#pragma unroll
        for (int kk = 0; kk < 9; kk++) {
            int ky = kk / 3, kx = kk - ky*3;
            const float* Tb = &sT[((yl + ky)*66 + xq*16 + kx)*12];
            uint32_t a[4];
            a[0] = __float_as_uint(Tb[lq*12 + lr]);
            a[1] = __float_as_uint(Tb[(lq+8)*12 + lr]);
            a[2] = __float_as_uint(Tb[lq*12 + lr + 4]);
            a[3] = __float_as_uint(Tb[(lq+8)*12 + lr + 4]);
            const float* Wb = &sW[kk*8*72];
#pragma unroll
            for (int nt = 0; nt < 8; nt++) {
                uint32_t bb[2];
                bb[0] = __float_as_uint(Wb[lr*72 + nt*8 + lq]);
                bb[1] = __float_as_uint(Wb[(lr+4)*72 + nt*8 + lq]);
                mma_tf32(acc[nt], a, bb);
            }
        }
    }

    // epilogue: c0:(x, co) c1:(x, co+1) c2:(x+8, co) c3:(x+8, co+1)
    int y = y0 + yl;
    int x = xq*16 + lq;
#pragma unroll
    for (int nt = 0; nt < 8; nt++) {
        int co = coh + nt*8 + lr*2;
        float b0 = bias[co], b1 = bias[co+1];
        size_t o0 = (((size_t)b*CH + co  )*64 + y)*64 + x;
        size_t o1 = (((size_t)b*CH + co+1)*64 + y)*64 + x;
        float v0 = fmaxf(acc[nt][0] + b0, 0.f);
        float v1 = fmaxf(acc[nt][1] + b1, 0.f);
        float v2 = fmaxf(acc[nt][2] + b0, 0.f);
        float v3 = fmaxf(acc[nt][3] + b1, 0.f);
        if (resid) {
            v0 += resid[o0]; v1 += resid[o1];
            v2 += resid[o0 + 8]; v3 += resid[o1 + 8];
        }
        out[o0] = v0; out[o1] = v1;
        out[o0 + 8] = v2; out[o1 + 8] = v3;
    }
}

// ---------------- launch ---------------------------------------------------
extern "C" void kernel_launch(void* const* d_in, const int* in_sizes, int n_in,
                              void* d_out, int out_size) {
    const float* noisy = (const float*)d_in[0];
    const float* aux   = (const float*)d_in[1];
    const float* gamma = (const float*)d_in[2];
    const float* beta  = (const float*)d_in[3];
    const float* inw   = (const float*)d_in[4];
    const float* cw    = (const float*)d_in[5];
    const float* cb    = (const float*)d_in[6];
    const float* alog  = (const float*)d_in[7];
    const float* dtb   = (const float*)d_in[8];
    const float* Dsk   = (const float*)d_in[9];
    const float* rmsw  = (const float*)d_in[10];
    const float* outw  = (const float*)d_in[11];
    const float* fw1   = (const float*)d_in[12];
    const float* fb1   = (const float*)d_in[13];
    const float* fw2   = (const float*)d_in[14];
    const float* fb2   = (const float*)d_in[15];
    float* out = (float*)d_out;

    void *p_res, *p_ff1;
    cudaGetSymbolAddress(&p_res, g_res);
    cudaGetSymbolAddress(&p_ff1, g_ff1);

    ln_kernel<<<2048, 256>>>(noisy, gamma, beta);
    gemm_inproj<<<dim3(6, 128), 256>>>(inw);
    conv1d_kernel<<<dim3(64, 3, 4), 256>>>(cw, cb);
    ssd_chunk<<<2048, 256>>>(alog, dtb);
    ssd_chain<<<64, 1024>>>();
    ssd_inter<<<2048, 256>>>();
    gate_kernel<<<2048, 256>>>(Dsk, rmsw);
    gemm_out<<<128, 256>>>(outw, noisy);
    conv3_tc<<<dim3(2, 32, 4), 256>>>((const float*)p_res, fw1, fb1, (float*)p_ff1, nullptr);
    conv3_tc<<<dim3(2, 32, 4), 256>>>((const float*)p_ff1, fw2, fb2, out, (const float*)p_res);

    // aux passthrough: second half of output
    if (out_size >= 2*LPOS*CH) {
        cudaMemcpyAsync(out + (size_t)LPOS*CH, aux, (size_t)LPOS*CH*sizeof(float),
                        cudaMemcpyDeviceToDevice, 0);
    }
}